// round 1
// baseline (speedup 1.0000x reference)
#include <cuda_runtime.h>
#include <cuda_bf16.h>

// ---------------- problem constants ----------------
#define B_  64
#define H_  512
#define W_  512
#define RAD 20              // radius = int(4*5 + 0.5)
#define KSZ 41

// ---------------- Gaussian weights (compile-time, exp(-t^2/50)) ----------------
// Values computed to ~1e-7 relative accuracy; normalization done in constexpr
// double so weights fold to FFMA immediates (rt_SMSP=1 on sm_103a).
constexpr double PHI[21] = {
    1.0,
    0.98019867, 0.92311635, 0.83527021, 0.72614903, 0.60653066,
    0.48675227, 0.37531110, 0.27803730, 0.19789870, 0.13533528,
    0.08892161, 0.05613478, 0.03404747, 0.01984109, 0.01110900,
    0.00597603, 0.00308871, 0.00153381, 0.00073181, 0.00033546
};

constexpr double ksum() {
    double s = PHI[0];
    for (int t = 1; t <= 20; ++t) s += 2.0 * PHI[t];
    return s;
}

struct W41 { float v[KSZ]; };

constexpr W41 make_w(double scale) {
    W41 w{};
    double s = ksum();
    for (int i = 0; i < KSZ; ++i) {
        int t = i - RAD; if (t < 0) t = -t;
        w.v[i] = (float)(scale * PHI[t] / s);
    }
    return w;
}

__device__ constexpr W41 WH = make_w(1.0);    // h-pass: plain normalized kernel
__device__ constexpr W41 WV = make_w(100.0);  // v-pass: folds 2*ALPHA; subtract ALPHA after

// ---------------- scratch (h-blurred fields) ----------------
__device__ float g_tdx[(size_t)B_ * H_ * W_];
__device__ float g_tdy[(size_t)B_ * H_ * W_];

__device__ __forceinline__ int reflect_once(int i, int n) {
    // valid for i in [-n, 2n) — one-period symmetric reflect (edge included)
    i = (i < 0) ? (-1 - i) : i;
    return (i >= n) ? (2 * n - 1 - i) : i;
}

// ---------------- kernel 1: horizontal blur of both fields ----------------
// grid = B*H blocks (one row each), 128 threads, 4 consecutive outputs/thread.
__global__ __launch_bounds__(128) void hblur_kernel(
    const float* __restrict__ rdx, const float* __restrict__ rdy)
{
    __shared__ float s0[W_ + 2 * RAD];   // 552
    __shared__ float s1[W_ + 2 * RAD];

    const int row = blockIdx.x;                 // 0 .. B*H-1
    const size_t rbase = (size_t)row * W_;
    const float* p0 = rdx + rbase;
    const float* p1 = rdy + rbase;

    for (int i = threadIdx.x; i < W_ + 2 * RAD; i += 128) {
        int c = reflect_once(i - RAD, W_);
        s0[i] = p0[c];
        s1[i] = p1[c];
    }
    __syncthreads();

    const int x0 = threadIdx.x * 4;
    float a0[4] = {0.f, 0.f, 0.f, 0.f};
    float a1[4] = {0.f, 0.f, 0.f, 0.f};

    // load each smem value once; feed all outputs that need it
    #pragma unroll
    for (int k = 0; k < KSZ + 3; ++k) {
        const float v0 = s0[x0 + k];
        const float v1 = s1[x0 + k];
        #pragma unroll
        for (int j = 0; j < 4; ++j) {
            const int t = k - j;
            if (t >= 0 && t < KSZ) {
                a0[j] = fmaf(v0, WH.v[t], a0[j]);
                a1[j] = fmaf(v1, WH.v[t], a1[j]);
            }
        }
    }

    *(float4*)(g_tdx + rbase + x0) = make_float4(a0[0], a0[1], a0[2], a0[3]);
    *(float4*)(g_tdy + rbase + x0) = make_float4(a1[0], a1[1], a1[2], a1[3]);
}

// ---------------- kernel 2: vertical blur + bilinear warp (fused) ----------------
// block = (32,8): 32 cols x 8 row-threads, 4 consecutive rows/thread -> 32x32 tile.
#define TTX 32
#define TTY 32

__global__ __launch_bounds__(256) void vwarp_kernel(
    const float* __restrict__ img, float* __restrict__ out)
{
    __shared__ float s0[(TTY + 2 * RAD) * TTX];   // 72*32 per field
    __shared__ float s1[(TTY + 2 * RAD) * TTX];

    const int x  = blockIdx.x * TTX + threadIdx.x;
    const int y0 = blockIdx.y * TTY;
    const int b  = blockIdx.z;
    const size_t base = (size_t)b * H_ * W_;

    for (int j = threadIdx.y; j < TTY + 2 * RAD; j += 8) {
        int y = reflect_once(y0 + j - RAD, H_);
        const size_t off = base + (size_t)y * W_ + x;
        s0[j * TTX + threadIdx.x] = g_tdx[off];
        s1[j * TTX + threadIdx.x] = g_tdy[off];
    }
    __syncthreads();

    const int r0 = threadIdx.y * 4;   // tile-local first output row
    float a0[4] = {0.f, 0.f, 0.f, 0.f};
    float a1[4] = {0.f, 0.f, 0.f, 0.f};

    #pragma unroll
    for (int k = 0; k < KSZ + 3; ++k) {
        const float v0 = s0[(r0 + k) * TTX + threadIdx.x];
        const float v1 = s1[(r0 + k) * TTX + threadIdx.x];
        #pragma unroll
        for (int j = 0; j < 4; ++j) {
            const int t = k - j;
            if (t >= 0 && t < KSZ) {
                a0[j] = fmaf(v0, WV.v[t], a0[j]);
                a1[j] = fmaf(v1, WV.v[t], a1[j]);
            }
        }
    }

    const float* im = img + base;
    #pragma unroll
    for (int j = 0; j < 4; ++j) {
        const int yo = y0 + r0 + j;
        const float dx = a0[j] - 50.0f;    // (2a*blur - a) fold
        const float dy = a1[j] - 50.0f;
        const float xx = (float)x  + dx;
        const float yy = (float)yo + dy;
        const float xf = floorf(xx);
        const float yf = floorf(yy);
        const float wx = xx - xf;
        const float wy = yy - yf;
        const int xi = (int)xf;
        const int yi = (int)yf;
        // coords bounded to [-51, 562] since |d| <= 50 -> one-period reflect ok
        const int x0r = reflect_once(xi,     W_);
        const int x1r = reflect_once(xi + 1, W_);
        const int y0r = reflect_once(yi,     H_);
        const int y1r = reflect_once(yi + 1, H_);

        const float v00 = __ldg(im + (size_t)y0r * W_ + x0r);
        const float v01 = __ldg(im + (size_t)y0r * W_ + x1r);
        const float v10 = __ldg(im + (size_t)y1r * W_ + x0r);
        const float v11 = __ldg(im + (size_t)y1r * W_ + x1r);

        const float top = v00 + wx * (v01 - v00);
        const float bot = v10 + wx * (v11 - v10);
        out[base + (size_t)yo * W_ + x] = top + wy * (bot - top);
    }
}

// ---------------- launch ----------------
extern "C" void kernel_launch(void* const* d_in, const int* in_sizes, int n_in,
                              void* d_out, int out_size)
{
    const float* x       = (const float*)d_in[0];  // [B,1,H,W]
    const float* rand_dx = (const float*)d_in[1];  // [B,H,W]
    const float* rand_dy = (const float*)d_in[2];  // [B,H,W]
    float* out = (float*)d_out;

    hblur_kernel<<<B_ * H_, 128>>>(rand_dx, rand_dy);

    dim3 grid(W_ / TTX, H_ / TTY, B_);
    dim3 block(TTX, 8);
    vwarp_kernel<<<grid, block>>>(x, out);
}